// round 13
// baseline (speedup 1.0000x reference)
#include <cuda_runtime.h>

// StateSpaceDiffusionModel: y[b,h,:] = causal_conv(u[b,h,:], f[h,:])
// reduced exactly to a scalar order-64 IIR+FIR (transposed direct form II):
//   y_t = c0*u_t + S[1]
//   S[i] <- S[i+1] + A'[i]*y_t + C'[i]*u_t   (merged delay line, i=1..64)
// A'[i] = a_{i-1} (1<=i<=64), C'[i] = c_i (1<=i<=63).
//
// R12 = champion R3/R11 body with ALL warp shuffles replaced by shared-memory
// exchange. In a 1-warp CTA, __syncthreads() is BAR.SYNC at the nw=1 floor
// (~3-7 cyc) and drains pending STS — one bar per iteration orders both the
// same-iteration y broadcast and the one-iteration-delayed boundary pair
// (parity double-buffered; parity == `half`, statically known).
// Arithmetic is bit-identical to R3 (expected rel_err 2.612269e-06 exactly).

#define HH 512
#define NN 64
#define BB 16
#define LL 2048

__device__ float g_a[HH * NN];
__device__ float g_c[HH * NN];

// ---------------- Kernel 1: per-head coefficients (trivial) ----------------
__global__ void coef_kernel(const float* __restrict__ k) {
    __shared__ float sh[NN];
    __shared__ float shd[NN];
    __shared__ float shP[NN];
    __shared__ float shsum;
    int h = blockIdx.x;
    int j = threadIdx.x;
    float kv = k[h * NN + j];
    float kc = fminf(fmaxf(kv, 1.0f / 16.0f), 1.0f);
    sh[j] = kc;
    __syncthreads();
    if (j == 0) {
        float s = 0.f;
        for (int i = 0; i < NN; i++) s += sh[i];
        shsum = s;
    }
    __syncthreads();
    float kn = kc / shsum;                       // L1-normalized clamped k
    float s = (j < NN - 1) ? (1.0f + kn) : kn;   // column L1 norm of (A + b k^T)
    float w = kn / s;                            // M[0, j]
    shd[j] = 1.0f / s;                           // M[j+1, j] subdiagonal
    __syncthreads();
    if (j == 0) {
        float P = 1.f;
        for (int i = 0; i < NN; i++) { shP[i] = P; P *= shd[i]; }
    }
    __syncthreads();
    float Pj = shP[j];
    g_a[h * NN + j] = w * Pj;    // IIR taps
    g_c[h * NN + j] = kv * Pj;   // FIR taps (original k!)
}

// ---------------- packed f32x2 helpers ----------------
typedef unsigned long long ull;
__device__ __forceinline__ ull pack2(float lo, float hi) {
    ull r; asm("mov.b64 %0, {%1,%2};" : "=l"(r) : "f"(lo), "f"(hi)); return r;
}
__device__ __forceinline__ void unpack2(ull v, float& lo, float& hi) {
    asm("mov.b64 {%0,%1}, %2;" : "=f"(lo), "=f"(hi) : "l"(v));
}
__device__ __forceinline__ ull fma2(ull a, ull b, ull c) {
    ull d; asm("fma.rn.f32x2 %0, %1, %2, %3;" : "=l"(d) : "l"(a), "l"(b), "l"(c)); return d;
}

// ---------------- Kernel 2: fused scan, smem exchange, 8 lanes/seq ----------
// Two timesteps per iteration. pair p = slots (2p+1, 2p+2), p = 0..31.
//   S''_p = S_{p+1} + Ae_p*y0 + Ao_p*y1 + Ce_p*u0 + Co_p*u1
// Warp = 4 sequences x 8 lanes; lane r owns pairs 4r..4r+3 (slots 8r+1..8r+8).
// Exchange (NO shuffles):
//   y broadcast: leader STS sh_y[g] -> BAR -> all lanes LDS (same iteration)
//   boundary sn: each lane STS fresh S[0] at iter end into sh_b[half][lane];
//                consumer reads sh_b[1-half][lane+1] next iteration (after the
//                same single BAR). Parity == `half` is compile-time static.
#define PD2 4   // float4 FIFO slots; each slot feeds 2 iterations (4 timesteps)

__global__ void __launch_bounds__(32)
scan_kernel(const float* __restrict__ u, float* __restrict__ y) {
    __shared__ ull sh_y[4];        // per-group y pair (same-iteration broadcast)
    __shared__ ull sh_b[2][33];    // boundary S[0] per lane, parity buffered

    int warp = blockIdx.x;            // one warp per CTA
    int lane = threadIdx.x & 31;
    int g = lane >> 3;   // sequence within warp (0..3)
    int r = lane & 7;    // lane within group (0..7)
    int seq = warp * 4 + g;           // 0..8191
    int h = seq & (HH - 1);
    const float4* ubase4 = (const float4*)(u + (size_t)seq * LL);
    float4* ybase4 = (float4*)(y + (size_t)seq * LL);

    const float* ah = g_a + h * NN;
    const float* ch = g_c + h * NN;

    ull Ae[4], Ao[4], Ce[4], Co[4], S[4];
#pragma unroll
    for (int i = 0; i < 4; i++) {
        int p = r * 4 + i;
        int i1 = 2 * p + 1, i2 = 2 * p + 2, i3 = 2 * p + 3;
        // A'[idx] = a[idx-1] for 1<=idx<=64 ; C'[idx] = c[idx] for 1<=idx<=63
        float A1 = (i1 <= 64) ? ah[i1 - 1] : 0.f;
        float A2 = (i2 <= 64) ? ah[i2 - 1] : 0.f;
        float A3 = (i3 <= 64) ? ah[i3 - 1] : 0.f;
        float C1 = (i1 <= 63) ? ch[i1] : 0.f;
        float C2 = (i2 <= 63) ? ch[i2] : 0.f;
        float C3 = (i3 <= 63) ? ch[i3] : 0.f;
        Ae[i] = pack2(A2, A3);
        Ao[i] = pack2(A1, A2);
        Ce[i] = pack2(C2, C3);
        Co[i] = pack2(C1, C2);
        S[i] = 0ull;
    }
    float c0h = ch[0], c1h = ch[1], a0h = ah[0];
    float SS1 = 0.f, SS2 = 0.f;   // unpacked old S[0] (valid on r==0)

    // prime exchange buffers with zeros (state starts at zero)
    sh_b[0][lane] = 0ull;
    sh_b[1][lane] = 0ull;
    if (lane < 4) sh_y[lane] = 0ull;
    if (lane == 0) { sh_b[0][32] = 0ull; sh_b[1][32] = 0ull; }
    __syncthreads();

    // prologue: fill FIFO (each slot covers 4 timesteps)
    float4 buf[PD2];
#pragma unroll
    for (int j = 0; j < PD2; j++)
        buf[j] = ubase4[j];

    const int NQ = LL / 4;  // 512 four-step chunks
    for (int q0 = 0; q0 < NQ; q0 += PD2) {
#pragma unroll
        for (int j = 0; j < PD2; j++) {
            int q = q0 + j;             // chunk index: timesteps 4q..4q+3
            float4 cur = buf[j];
            int qp = q + PD2;
            if (qp > NQ - 1) qp = NQ - 1;   // clamped refill (unused if OOB)
            buf[j] = ubase4[qp];

            float2 yout01, yout23;
#pragma unroll
            for (int half = 0; half < 2; half++) {
                // iteration parity: (2q + half) & 1 == half (static!)
                float u0 = half ? cur.z : cur.x;
                float u1 = half ? cur.w : cur.y;

                // leader computes y from its old S[0] (garbage off-leader)
                float y0 = fmaf(c0h, u0, SS1);
                float y1 = fmaf(a0h, y0, fmaf(c1h, u0, fmaf(c0h, u1, SS2)));
                if (r == 0) sh_y[g] = pack2(y0, y1);       // STS.64

                __syncthreads();   // nw=1 BAR: ~3-7 cyc, drains STS (y + prev boundary)

                ull ypk = sh_y[g];                          // LDS broadcast
                ull sn = sh_b[1 - half][lane + 1];          // boundary from prev iter
                if (r == 7) sn = 0ull;

                float y0b, y1b; unpack2(ypk, y0b, y1b);
                ull y0pk = pack2(y0b, y0b), y1pk = pack2(y1b, y1b);
                ull u0pk = pack2(u0, u0), u1pk = pack2(u1, u1);
#pragma unroll
                for (int i = 0; i < 3; i++)
                    S[i] = fma2(Ae[i], y0pk, fma2(Ao[i], y1pk,
                            fma2(Ce[i], u0pk, fma2(Co[i], u1pk, S[i + 1]))));
                S[3] = fma2(Ae[3], y0pk, fma2(Ao[3], y1pk,
                         fma2(Ce[3], u0pk, fma2(Co[3], u1pk, sn))));

                sh_b[half][lane] = S[0];   // boundary for NEXT iteration
                unpack2(S[0], SS1, SS2);

                if (half == 0) yout01 = make_float2(y0b, y1b);
                else           yout23 = make_float2(y0b, y1b);
            }

            if (r == 0)
                ybase4[q] = make_float4(yout01.x, yout01.y, yout23.x, yout23.y);
        }
    }
}

extern "C" void kernel_launch(void* const* d_in, const int* in_sizes, int n_in,
                              void* d_out, int out_size) {
    const float* u = (const float*)d_in[0];
    const float* k = (const float*)d_in[1];
    if (n_in >= 2 && in_sizes[0] == HH * NN) {  // defensive: swap if order differs
        u = (const float*)d_in[1];
        k = (const float*)d_in[0];
    }
    float* y = (float*)d_out;

    coef_kernel<<<HH, NN>>>(k);
    // 8192 sequences, 4 per warp, ONE warp per CTA -> 2048 CTAs
    scan_kernel<<<(BB * HH) / 4, 32>>>(u, y);
}